// round 16
// baseline (speedup 1.0000x reference)
#include <cuda_runtime.h>
#include <cuda_fp16.h>
#include <cstdint>

// Problem constants
#define BATCH   2
#define S_LEN   2048
#define D_MODEL 1024
#define NH      16
#define HD      64
#define WINDOW  256
#define TOKENS  (BATCH * S_LEN)               // 4096
#define OUT_ELEMS ((size_t)TOKENS * D_MODEL)  // 4194304

// ---------------- device scratch (allocation-free rule) ----------------
__device__ __align__(128) __half g_qh [BATCH * NH * S_LEN * HD];     // fp16 Q (pre-scaled)
__device__ __align__(128) __half g_kh [BATCH * NH * S_LEN * HD];     // fp16 K
__device__ __align__(128) __half g_vh [BATCH * NH * S_LEN * HD];     // fp16 V
__device__ __align__(128) __half g_xh  [(size_t)TOKENS * D_MODEL];      // x hi
__device__ __align__(128) __half g_ah  [(size_t)TOKENS * D_MODEL];      // attn out hi
__device__ __align__(128) __half g_wat [(size_t)3 * D_MODEL * D_MODEL]; // w_attn^T hi
__device__ __align__(128) __half g_wpt [(size_t)D_MODEL * D_MODEL];     // w_proj^T hi

// ---------------- helpers ----------------
__device__ __forceinline__ uint32_t smem_u32(const void* p) {
    uint32_t a;
    asm("{ .reg .u64 t; cvta.to.shared.u64 t, %1; cvt.u32.u64 %0, t; }" : "=r"(a) : "l"(p));
    return a;
}
__device__ __forceinline__ void cp16(uint32_t saddr, const void* g) {
    asm volatile("cp.async.cg.shared.global [%0], [%1], 16;" :: "r"(saddr), "l"(g));
}
#define CP_COMMIT() asm volatile("cp.async.commit_group;" ::: "memory")
#define CP_WAIT1()  asm volatile("cp.async.wait_group 1;" ::: "memory")
#define CP_WAIT0()  asm volatile("cp.async.wait_group 0;" ::: "memory")

__device__ __forceinline__ void ldmx4(uint32_t* r, uint32_t addr) {
    asm volatile("ldmatrix.sync.aligned.m8n8.x4.shared.b16 {%0,%1,%2,%3}, [%4];"
                 : "=r"(r[0]), "=r"(r[1]), "=r"(r[2]), "=r"(r[3]) : "r"(addr));
}
__device__ __forceinline__ void ldmx4t(uint32_t* r, uint32_t addr) {
    asm volatile("ldmatrix.sync.aligned.m8n8.x4.trans.shared.b16 {%0,%1,%2,%3}, [%4];"
                 : "=r"(r[0]), "=r"(r[1]), "=r"(r[2]), "=r"(r[3]) : "r"(addr));
}
__device__ __forceinline__ void mma16816(float* c, const uint32_t* a, const uint32_t* b) {
    asm volatile(
        "mma.sync.aligned.m16n8k16.row.col.f32.f16.f16.f32 "
        "{%0,%1,%2,%3}, {%4,%5,%6,%7}, {%8,%9}, {%0,%1,%2,%3};"
        : "+f"(c[0]), "+f"(c[1]), "+f"(c[2]), "+f"(c[3])
        : "r"(a[0]), "r"(a[1]), "r"(a[2]), "r"(a[3]), "r"(b[0]), "r"(b[1]));
}
__device__ __forceinline__ uint32_t h2pack(float a, float b) {
    __half2 t = __floats2half2_rn(a, b);
    return *reinterpret_cast<uint32_t*>(&t);
}

// ---------------- conversion kernels ----------------
__global__ void convAh_k(const float* __restrict__ A, __half* __restrict__ O, int total4)
{
    int idx = blockIdx.x * blockDim.x + threadIdx.x;
    if (idx >= total4) return;
    float4 v = *(const float4*)&A[(size_t)idx * 4];
    uint2 H = {h2pack(v.x, v.y), h2pack(v.z, v.w)};
    *(uint2*)&O[(size_t)idx * 4] = H;
}
__global__ void convBth_k(const float* __restrict__ W, __half* __restrict__ O, int N)
{
    __shared__ float tile[32][33];
    const int k0 = blockIdx.y * 32, n0 = blockIdx.x * 32;
    const int tx = threadIdx.x;   // 0..7
    const int ty = threadIdx.y;   // 0..31
    float4 w4 = *(const float4*)&W[(size_t)(k0 + ty) * N + n0 + tx * 4];
    tile[ty][tx * 4 + 0] = w4.x;
    tile[ty][tx * 4 + 1] = w4.y;
    tile[ty][tx * 4 + 2] = w4.z;
    tile[ty][tx * 4 + 3] = w4.w;
    __syncthreads();
    const int tid = ty * 8 + tx;
    const int nr = tid >> 3;
    const int kq = tid & 7;
    uint2 H = {h2pack(tile[kq * 4 + 0][nr], tile[kq * 4 + 1][nr]),
               h2pack(tile[kq * 4 + 2][nr], tile[kq * 4 + 3][nr])};
    *(uint2*)&O[(size_t)(n0 + nr) * D_MODEL + k0 + kq * 4] = H;
}

// ---------------- mma.sync GEMM: 128x64 block tile, 3 CTAs/SM (6 warps/SMSP) ----------------
// 8 warps at 64x16 warp tiles (2M x 4N). Double-buffered cp.async (A 128 rows + B 64 rows).
#define A_TILE      18432         // 128 rows * 144B
#define B_TILE      9216          // 64 rows * 144B
#define STAGE_BYTES 27648
#define GEMM_SMEM   55296
#define KEL         1024
#define NCH         16

template<int MODE>
__global__ __launch_bounds__(256, 3) void gemm_mma(const __half* __restrict__ A,
                                                   const __half* __restrict__ Bt,
                                                   const float* __restrict__ bias,
                                                   float* __restrict__ C,
                                                   float* __restrict__ KV)
{
    extern __shared__ char smem[];
    const uint32_t sb = smem_u32(smem);
    const int tid = threadIdx.x;
    const int wid = tid >> 5, lid = tid & 31;
    const int m0 = blockIdx.y * 128, n0 = blockIdx.x * 64;
    const int mbase = (wid & 1) * 64;      // 2 M warps
    const int nbase = (wid >> 1) * 16;     // 4 N warps

    const char* Abase = (const char*)(A  + (size_t)m0 * KEL);
    const char* Bbase = (const char*)(Bt + (size_t)n0 * KEL);

    const uint32_t a_row_off = (uint32_t)((mbase + ((lid >> 3) & 1) * 8 + (lid & 7)) * 144
                                          + ((lid >> 4) * 8) * 2);
    const uint32_t b_row_off = (uint32_t)((nbase + ((lid >> 4) & 1) * 8 + (lid & 7)) * 144
                                          + (((lid >> 3) & 1) * 8) * 2);

    float acc[4][2][4];
#pragma unroll
    for (int mt = 0; mt < 4; mt++)
#pragma unroll
        for (int nt = 0; nt < 2; nt++)
#pragma unroll
            for (int i = 0; i < 4; i++) acc[mt][nt][i] = 0.f;

#define PREFETCH(c, buf)                                                            \
    {                                                                               \
        const size_t kbyte = (size_t)(c) * 128;                                     \
        const uint32_t base = sb + (buf) * STAGE_BYTES;                             \
        _Pragma("unroll")                                                           \
        for (int i = 0; i < 6; i++) {                                               \
            int idx = tid + i * 256;                                                \
            if (idx < 1024) {                                                       \
                int row = idx >> 3, seg = idx & 7;                                  \
                cp16(base + row * 144 + seg * 16,                                   \
                     Abase + (size_t)row * (KEL * 2) + kbyte + seg * 16);           \
            } else {                                                                \
                int j = idx - 1024;                                                 \
                int row = j >> 3, seg = j & 7;                                      \
                cp16(base + A_TILE + row * 144 + seg * 16,                          \
                     Bbase + (size_t)row * (KEL * 2) + kbyte + seg * 16);           \
            }                                                                       \
        }                                                                           \
    }

    PREFETCH(0, 0); CP_COMMIT();
    PREFETCH(1, 1); CP_COMMIT();

    for (int c = 0; c < NCH; c++) {
        if (c == NCH - 1) { CP_WAIT0(); } else { CP_WAIT1(); }
        __syncthreads();
        const uint32_t abuf = sb + (c & 1) * STAGE_BYTES;
        const uint32_t bbuf = abuf + A_TILE;
#pragma unroll
        for (int ks = 0; ks < 4; ks++) {
            const uint32_t kb = (uint32_t)ks * 32;
            uint32_t ar[4][4];
            uint32_t br[2][2];
#pragma unroll
            for (int mt = 0; mt < 4; mt++)
                ldmx4(ar[mt], abuf + a_row_off + mt * (16 * 144) + kb);
            {
                uint32_t r[4];
                ldmx4(r, bbuf + b_row_off + kb);
                br[0][0] = r[0]; br[0][1] = r[1];
                br[1][0] = r[2]; br[1][1] = r[3];
            }
#pragma unroll
            for (int mt = 0; mt < 4; mt++)
#pragma unroll
                for (int nt = 0; nt < 2; nt++)
                    mma16816(acc[mt][nt], ar[mt], br[nt]);
        }
        __syncthreads();
        if (c + 2 < NCH) { PREFETCH(c + 2, c & 1); CP_COMMIT(); }
    }
#undef PREFETCH

    const int lrow = lid >> 2;
    const int lcol = (lid & 3) * 2;
#pragma unroll
    for (int mt = 0; mt < 4; mt++) {
        const int gm = m0 + mbase + mt * 16 + lrow;
#pragma unroll
        for (int nt = 0; nt < 2; nt++) {
            const int gn = n0 + nbase + nt * 8 + lcol;
            if (MODE == 0) {
                const float b0 = bias[gn], b1 = bias[gn + 1];
                float2 v0 = {acc[mt][nt][0] + b0, acc[mt][nt][1] + b1};
                float2 v1 = {acc[mt][nt][2] + b0, acc[mt][nt][3] + b1};
                *(float2*)&C[(size_t)gm * D_MODEL + gn] = v0;
                *(float2*)&C[(size_t)(gm + 8) * D_MODEL + gn] = v1;
            } else {
                const float b0 = bias[gn], b1 = bias[gn + 1];
                const int sec = gn >> 10, fr = gn & 1023;
                const int hh = fr >> 6, dd = fr & 63;
#pragma unroll
                for (int e2 = 0; e2 < 2; e2++) {
                    const int row = gm + e2 * 8;
                    const int bb = row >> 11, s = row & 2047;
                    float2 w = {acc[mt][nt][e2 * 2 + 0] + b0,
                                acc[mt][nt][e2 * 2 + 1] + b1};
                    const size_t base = (((size_t)bb * NH + hh) * S_LEN + s) * HD + dd;
                    if (sec == 0) {
                        *(uint32_t*)&g_qh[base] = h2pack(w.x * 0.125f, w.y * 0.125f);
                    } else {
                        const size_t kvb =
                            ((((size_t)bb * 2 + (sec - 1)) * NH + hh) * S_LEN + s) * HD + dd;
                        *(float2*)&KV[kvb] = w;    // fp32 `present`
                        if (sec == 1) *(uint32_t*)&g_kh[base] = h2pack(w.x, w.y);
                        else          *(uint32_t*)&g_vh[base] = h2pack(w.x, w.y);
                    }
                }
            }
        }
    }
}

// ---------------- tensor-core flash attention, K/V tile double-buffered ----------------
// Smem: Q (9216) + 2 x (K+V) stages (2 x 18432) = 46080 B -> 4 CTAs/SM.
#define ATTN_SMEM_BYTES 46080

__global__ __launch_bounds__(128, 4) void attn_k()
{
    extern __shared__ char smem[];
    const uint32_t sb = smem_u32(smem);
    const uint32_t sQ = sb;

    const int bid = blockIdx.x;
    const int qt = bid & 31;
    const int h  = (bid >> 5) & 15;
    const int b  = bid >> 9;
    const int qs = qt * 64;

    const int tid = threadIdx.x;
    const int wid = tid >> 5, lid = tid & 31;
    const int mbase = wid * 16;

    const __half* Qg = g_qh + ((size_t)(b * NH + h) * S_LEN + qs) * HD;
    const __half* Kg = g_kh + ((size_t)(b * NH + h) * S_LEN) * HD;
    const __half* Vg = g_vh + ((size_t)(b * NH + h) * S_LEN) * HD;

    const int start = (qs < 256) ? ((256 - qs) >> 6) : 0;

    // Q tile (group 0, together with tile `start`)
    for (int idx = tid; idx < 512; idx += 128) {
        const int row = idx >> 3, seg = idx & 7;
        cp16(sQ + row * 144 + seg * 16, (const char*)Qg + row * 128 + seg * 16);
    }

#define LOAD_TILE(kt, buf)                                                          \
    {                                                                               \
        const int ks_ = qs - 256 + (kt) * 64;                                       \
        const uint32_t kbuf = sb + 9216 + (buf) * 18432;                            \
        for (int idx = tid; idx < 512; idx += 128) {                                \
            const int row = idx >> 3, seg = idx & 7;                                \
            const int gj = ks_ + row;                                               \
            if (gj >= 0) {                                                          \
                cp16(kbuf + row * 144 + seg * 16,                                   \
                     (const char*)Kg + (size_t)gj * 128 + seg * 16);                \
                cp16(kbuf + 9216 + row * 144 + seg * 16,                            \
                     (const char*)Vg + (size_t)gj * 128 + seg * 16);                \
            } else {                                                                \
                uint4 z = {0u, 0u, 0u, 0u};                                         \
                *(uint4*)(smem + 9216 + (buf) * 18432 + row * 144 + seg * 16) = z;  \
                *(uint4*)(smem + 9216 + (buf) * 18432 + 9216 + row * 144 + seg * 16) = z; \
            }                                                                       \
        }                                                                           \
    }

    LOAD_TILE(start, start & 1);
    CP_COMMIT();

    const uint32_t a_off = (uint32_t)((mbase + ((lid >> 3) & 1) * 8 + (lid & 7)) * 144
                                      + ((lid >> 4) * 8) * 2);
    const uint32_t bK_off = (uint32_t)(((((lid >> 4) & 1) * 8) + (lid & 7)) * 144
                                       + (((lid >> 3) & 1) * 8) * 2);
    const int vmid = lid >> 3;
    const uint32_t bV_off = (uint32_t)((((vmid & 1) * 8 + (lid & 7)) * 144)
                                       + ((vmid >> 1) * 8) * 2);

    const int r0 = lid >> 2;
    const int qcol = (lid & 3) * 2;

    float o[8][4];
#pragma unroll
    for (int t = 0; t < 8; t++)
#pragma unroll
        for (int i = 0; i < 4; i++) o[t][i] = 0.f;
    float m0r = -1e29f, m1r = -1e29f, rs0 = 0.f, rs1 = 0.f;

    for (int kt = start; kt < 5; kt++) {
        const int ks = qs - 256 + kt * 64;

        // prefetch next tile into the other buffer, then wait for tile kt
        if (kt + 1 < 5) {
            LOAD_TILE(kt + 1, (kt + 1) & 1);
            CP_COMMIT();
            CP_WAIT1();
        } else {
            CP_WAIT0();
        }
        __syncthreads();   // tile kt visible; all threads done with buffer (kt+1)&1's old data

        const uint32_t sK = sb + 9216 + (kt & 1) * 18432;
        const uint32_t sV = sK + 9216;

        float c[8][4];
#pragma unroll
        for (int t = 0; t < 8; t++)
#pragma unroll
            for (int i = 0; i < 4; i++) c[t][i] = 0.f;
#pragma unroll
        for (int ks4 = 0; ks4 < 4; ks4++) {
            const uint32_t kb = (uint32_t)ks4 * 32;
            uint32_t aq[4];
            ldmx4(aq, sQ + a_off + kb);
            uint32_t bk[8][2];
#pragma unroll
            for (int p = 0; p < 4; p++) {
                uint32_t r[4];
                ldmx4(r, sK + bK_off + p * (16 * 144) + kb);
                bk[p * 2][0] = r[0]; bk[p * 2][1] = r[1];
                bk[p * 2 + 1][0] = r[2]; bk[p * 2 + 1][1] = r[3];
            }
#pragma unroll
            for (int t = 0; t < 8; t++)
                mma16816(c[t], aq, bk[t]);
        }

        const int gi0 = qs + mbase + r0, gi1 = gi0 + 8;
#pragma unroll
        for (int t = 0; t < 8; t++) {
            const int cb = ks + t * 8 + qcol;
#pragma unroll
            for (int e = 0; e < 2; e++) {
                const int gj = cb + e;
                if (!(gj >= 0 && gj <= gi0 && gj > gi0 - WINDOW)) c[t][e]     = -1e30f;
                if (!(gj >= 0 && gj <= gi1 && gj > gi1 - WINDOW)) c[t][e + 2] = -1e30f;
            }
        }

        float mx0 = -1e30f, mx1 = -1e30f;
#pragma unroll
        for (int t = 0; t < 8; t++) {
            mx0 = fmaxf(mx0, fmaxf(c[t][0], c[t][1]));
            mx1 = fmaxf(mx1, fmaxf(c[t][2], c[t][3]));
        }
#pragma unroll
        for (int w = 1; w < 4; w <<= 1) {
            mx0 = fmaxf(mx0, __shfl_xor_sync(0xffffffffu, mx0, w));
            mx1 = fmaxf(mx1, __shfl_xor_sync(0xffffffffu, mx1, w));
        }
        const float mn0 = fmaxf(m0r, mx0), mn1 = fmaxf(m1r, mx1);
        const float al0 = __expf(m0r - mn0), al1 = __expf(m1r - mn1);

        uint32_t pa[4][4];
        float ls0 = 0.f, ls1 = 0.f;
#pragma unroll
        for (int t = 0; t < 8; t++) {
            const float p0 = __expf(c[t][0] - mn0);
            const float p1 = __expf(c[t][1] - mn0);
            const float p2 = __expf(c[t][2] - mn1);
            const float p3 = __expf(c[t][3] - mn1);
            ls0 += p0 + p1; ls1 += p2 + p3;
            pa[t >> 1][(t & 1) * 2 + 0] = h2pack(p0, p1);
            pa[t >> 1][(t & 1) * 2 + 1] = h2pack(p2, p3);
        }
#pragma unroll
        for (int w = 1; w < 4; w <<= 1) {
            ls0 += __shfl_xor_sync(0xffffffffu, ls0, w);
            ls1 += __shfl_xor_sync(0xffffffffu, ls1, w);
        }
        rs0 = rs0 * al0 + ls0;
        rs1 = rs1 * al1 + ls1;
        m0r = mn0; m1r = mn1;
#pragma unroll
        for (int t = 0; t < 8; t++) {
            o[t][0] *= al0; o[t][1] *= al0;
            o[t][2] *= al1; o[t][3] *= al1;
        }

#pragma unroll
        for (int kk = 0; kk < 4; kk++) {
            uint32_t bv[8][2];
#pragma unroll
            for (int p = 0; p < 4; p++) {
                uint32_t r[4];
                ldmx4t(r, sV + bV_off + kk * (16 * 144) + p * 32);
                bv[p * 2][0] = r[0]; bv[p * 2][1] = r[1];
                bv[p * 2 + 1][0] = r[2]; bv[p * 2 + 1][1] = r[3];
            }
#pragma unroll
            for (int t = 0; t < 8; t++)
                mma16816(o[t], pa[kk], bv[t]);
        }
        __syncthreads();   // all threads done with buffer kt&1 before it is refilled
    }
#undef LOAD_TILE

    // epilogue: normalize, fp16 hi into g_ah
    const float ri0 = 1.f / rs0, ri1 = 1.f / rs1;
    const size_t mrow0 = (size_t)b * S_LEN + qs + mbase + r0;
    __half* row0 = g_ah + mrow0 * D_MODEL;
    __half* row1 = row0 + (size_t)8 * D_MODEL;
    const int kc = h * HD + qcol;
#pragma unroll
    for (int t = 0; t < 8; t++) {
        const int k = kc + t * 8;
        *(uint32_t*)&row0[k] = h2pack(o[t][0] * ri0, o[t][1] * ri0);
        *(uint32_t*)&row1[k] = h2pack(o[t][2] * ri1, o[t][3] * ri1);
    }
}

// ---------------------------------------------------------------------------
extern "C" void kernel_launch(void* const* d_in, const int* in_sizes, int n_in,
                              void* d_out, int out_size)
{
    const float* x      = (const float*)d_in[0];
    const float* w_attn = (const float*)d_in[1];
    const float* b_attn = (const float*)d_in[2];
    const float* w_proj = (const float*)d_in[3];
    const float* b_proj = (const float*)d_in[4];
    float* out = (float*)d_out;
    float* kv  = out + OUT_ELEMS;

    cudaFuncSetAttribute(attn_k, cudaFuncAttributeMaxDynamicSharedMemorySize, ATTN_SMEM_BYTES);
    cudaFuncSetAttribute(gemm_mma<0>, cudaFuncAttributeMaxDynamicSharedMemorySize, GEMM_SMEM);
    cudaFuncSetAttribute(gemm_mma<1>, cudaFuncAttributeMaxDynamicSharedMemorySize, GEMM_SMEM);

    __half *xh, *ah, *wat, *wpt;
    cudaGetSymbolAddress((void**)&xh,  g_xh);
    cudaGetSymbolAddress((void**)&ah,  g_ah);
    cudaGetSymbolAddress((void**)&wat, g_wat);
    cudaGetSymbolAddress((void**)&wpt, g_wpt);

    // 1) conversions: x, w_attn^T, w_proj^T -> fp16 hi
    convAh_k<<<(TOKENS * 256 + 255) / 256, 256>>>(x, xh, TOKENS * 256);
    {
        dim3 blk(8, 32);
        convBth_k<<<dim3(3 * D_MODEL / 32, D_MODEL / 32), blk>>>(w_attn, wat, 3 * D_MODEL);
        convBth_k<<<dim3(D_MODEL / 32, D_MODEL / 32),     blk>>>(w_proj, wpt, D_MODEL);
    }

    // 2) QKV projection (K=1024, 128x64 tiles): fp16 Q/K/V + fp32 present tail
    gemm_mma<1><<<dim3(3 * D_MODEL / 64, TOKENS / 128), 256, GEMM_SMEM>>>(
        xh, wat, b_attn, nullptr, kv);

    // 3) tensor-core flash attention (double-buffered K/V) -> g_ah
    attn_k<<<BATCH * NH * (S_LEN / 64), 128, ATTN_SMEM_BYTES>>>();

    // 4) output projection (K=1024) -> d_out head
    gemm_mma<0><<<dim3(D_MODEL / 64, TOKENS / 128), 256, GEMM_SMEM>>>(
        ah, wpt, b_proj, out, nullptr);
}

// round 17
// speedup vs baseline: 1.1236x; 1.1236x over previous
#include <cuda_runtime.h>
#include <cuda_fp16.h>
#include <cstdint>

// Problem constants
#define BATCH   2
#define S_LEN   2048
#define D_MODEL 1024
#define NH      16
#define HD      64
#define WINDOW  256
#define TOKENS  (BATCH * S_LEN)               // 4096
#define OUT_ELEMS ((size_t)TOKENS * D_MODEL)  // 4194304

// ---------------- device scratch (allocation-free rule) ----------------
__device__ __align__(128) __half g_qh [BATCH * NH * S_LEN * HD];     // fp16 Q (pre-scaled)
__device__ __align__(128) __half g_kh [BATCH * NH * S_LEN * HD];     // fp16 K
__device__ __align__(128) __half g_vh [BATCH * NH * S_LEN * HD];     // fp16 V
__device__ __align__(128) __half g_xh  [(size_t)TOKENS * D_MODEL];      // x hi
__device__ __align__(128) __half g_ah  [(size_t)TOKENS * D_MODEL];      // attn out hi
__device__ __align__(128) __half g_wat [(size_t)3 * D_MODEL * D_MODEL]; // w_attn^T hi
__device__ __align__(128) __half g_wpt [(size_t)D_MODEL * D_MODEL];     // w_proj^T hi

// ---------------- helpers ----------------
__device__ __forceinline__ uint32_t smem_u32(const void* p) {
    uint32_t a;
    asm("{ .reg .u64 t; cvta.to.shared.u64 t, %1; cvt.u32.u64 %0, t; }" : "=r"(a) : "l"(p));
    return a;
}
__device__ __forceinline__ void cp16(uint32_t saddr, const void* g) {
    asm volatile("cp.async.cg.shared.global [%0], [%1], 16;" :: "r"(saddr), "l"(g));
}
#define CP_COMMIT() asm volatile("cp.async.commit_group;" ::: "memory")
#define CP_WAIT1()  asm volatile("cp.async.wait_group 1;" ::: "memory")
#define CP_WAIT0()  asm volatile("cp.async.wait_group 0;" ::: "memory")

__device__ __forceinline__ void ldmx4(uint32_t* r, uint32_t addr) {
    asm volatile("ldmatrix.sync.aligned.m8n8.x4.shared.b16 {%0,%1,%2,%3}, [%4];"
                 : "=r"(r[0]), "=r"(r[1]), "=r"(r[2]), "=r"(r[3]) : "r"(addr));
}
__device__ __forceinline__ void ldmx4t(uint32_t* r, uint32_t addr) {
    asm volatile("ldmatrix.sync.aligned.m8n8.x4.trans.shared.b16 {%0,%1,%2,%3}, [%4];"
                 : "=r"(r[0]), "=r"(r[1]), "=r"(r[2]), "=r"(r[3]) : "r"(addr));
}
__device__ __forceinline__ void mma16816(float* c, const uint32_t* a, const uint32_t* b) {
    asm volatile(
        "mma.sync.aligned.m16n8k16.row.col.f32.f16.f16.f32 "
        "{%0,%1,%2,%3}, {%4,%5,%6,%7}, {%8,%9}, {%0,%1,%2,%3};"
        : "+f"(c[0]), "+f"(c[1]), "+f"(c[2]), "+f"(c[3])
        : "r"(a[0]), "r"(a[1]), "r"(a[2]), "r"(a[3]), "r"(b[0]), "r"(b[1]));
}
__device__ __forceinline__ uint32_t h2pack(float a, float b) {
    __half2 t = __floats2half2_rn(a, b);
    return *reinterpret_cast<uint32_t*>(&t);
}

// ---------------- conversion kernels ----------------
__global__ void convAh_k(const float* __restrict__ A, __half* __restrict__ O, int total4)
{
    int idx = blockIdx.x * blockDim.x + threadIdx.x;
    if (idx >= total4) return;
    float4 v = *(const float4*)&A[(size_t)idx * 4];
    uint2 H = {h2pack(v.x, v.y), h2pack(v.z, v.w)};
    *(uint2*)&O[(size_t)idx * 4] = H;
}
__global__ void convBth_k(const float* __restrict__ W, __half* __restrict__ O, int N)
{
    __shared__ float tile[32][33];
    const int k0 = blockIdx.y * 32, n0 = blockIdx.x * 32;
    const int tx = threadIdx.x;   // 0..7
    const int ty = threadIdx.y;   // 0..31
    float4 w4 = *(const float4*)&W[(size_t)(k0 + ty) * N + n0 + tx * 4];
    tile[ty][tx * 4 + 0] = w4.x;
    tile[ty][tx * 4 + 1] = w4.y;
    tile[ty][tx * 4 + 2] = w4.z;
    tile[ty][tx * 4 + 3] = w4.w;
    __syncthreads();
    const int tid = ty * 8 + tx;
    const int nr = tid >> 3;
    const int kq = tid & 7;
    uint2 H = {h2pack(tile[kq * 4 + 0][nr], tile[kq * 4 + 1][nr]),
               h2pack(tile[kq * 4 + 2][nr], tile[kq * 4 + 3][nr])};
    *(uint2*)&O[(size_t)(n0 + nr) * D_MODEL + k0 + kq * 4] = H;
}

// ---------------- mma.sync GEMM (R15 winner: 128x128 tile, 2 CTAs/SM, K=1024) ----------------
#define TILE_BYTES  18432
#define BUF_BYTES   36864
#define GEMM_SMEM   110592
#define KEL         1024
#define NCH         16

template<int MODE>
__global__ __launch_bounds__(256, 2) void gemm_mma(const __half* __restrict__ A,
                                                   const __half* __restrict__ Bt,
                                                   const float* __restrict__ bias,
                                                   float* __restrict__ C,
                                                   float* __restrict__ KV)
{
    extern __shared__ char smem[];
    const uint32_t sb = smem_u32(smem);
    const int tid = threadIdx.x;
    const int wid = tid >> 5, lid = tid & 31;
    const int m0 = blockIdx.y * 128, n0 = blockIdx.x * 128;
    const int mbase = (wid & 1) * 64;
    const int nbase = (wid >> 1) * 32;

    const char* Abase = (const char*)(A  + (size_t)m0 * KEL);
    const char* Bbase = (const char*)(Bt + (size_t)n0 * KEL);

    const uint32_t a_row_off = (uint32_t)((mbase + ((lid >> 3) & 1) * 8 + (lid & 7)) * 144
                                          + ((lid >> 4) * 8) * 2);
    const uint32_t b_row_off = (uint32_t)((nbase + ((lid >> 4) & 1) * 8 + (lid & 7)) * 144
                                          + (((lid >> 3) & 1) * 8) * 2);

    float acc[4][4][4];
#pragma unroll
    for (int mt = 0; mt < 4; mt++)
#pragma unroll
        for (int nt = 0; nt < 4; nt++)
#pragma unroll
            for (int i = 0; i < 4; i++) acc[mt][nt][i] = 0.f;

#define PREFETCH(c, buf)                                                          \
    {                                                                             \
        const size_t kbyte = (size_t)(c) * 128;                                   \
        const uint32_t abuf = sb + (buf) * BUF_BYTES;                             \
        const uint32_t bbuf = abuf + TILE_BYTES;                                  \
        _Pragma("unroll")                                                         \
        for (int i = 0; i < 4; i++) {                                             \
            int idx = tid + i * 256;                                              \
            int row = idx >> 3, seg = idx & 7;                                    \
            uint32_t so = row * 144 + seg * 16;                                   \
            cp16(abuf + so, Abase + (size_t)row * (KEL * 2) + kbyte + seg * 16);  \
            cp16(bbuf + so, Bbase + (size_t)row * (KEL * 2) + kbyte + seg * 16);  \
        }                                                                         \
    }

    PREFETCH(0, 0); CP_COMMIT();
    PREFETCH(1, 1); CP_COMMIT();

    int buf = 0;
    for (int c = 0; c < NCH; c++) {
        if (c == NCH - 1) { CP_WAIT0(); } else { CP_WAIT1(); }
        __syncthreads();
        if (c + 2 < NCH) {
            int nbuf = buf + 2; if (nbuf >= 3) nbuf -= 3;
            PREFETCH(c + 2, nbuf);
            CP_COMMIT();
        }
        const uint32_t abuf = sb + buf * BUF_BYTES;
        const uint32_t bbuf = abuf + TILE_BYTES;
#pragma unroll
        for (int ks = 0; ks < 4; ks++) {
            const uint32_t kb = (uint32_t)ks * 32;
            uint32_t ar[4][4];
            uint32_t br[4][2];
#pragma unroll
            for (int mt = 0; mt < 4; mt++)
                ldmx4(ar[mt], abuf + a_row_off + mt * (16 * 144) + kb);
#pragma unroll
            for (int p = 0; p < 2; p++) {
                uint32_t r[4];
                ldmx4(r, bbuf + b_row_off + p * (16 * 144) + kb);
                br[p * 2][0] = r[0]; br[p * 2][1] = r[1];
                br[p * 2 + 1][0] = r[2]; br[p * 2 + 1][1] = r[3];
            }
#pragma unroll
            for (int mt = 0; mt < 4; mt++)
#pragma unroll
                for (int nt = 0; nt < 4; nt++)
                    mma16816(acc[mt][nt], ar[mt], br[nt]);
        }
        if (++buf == 3) buf = 0;
    }
#undef PREFETCH

    const int lrow = lid >> 2;
    const int lcol = (lid & 3) * 2;
#pragma unroll
    for (int mt = 0; mt < 4; mt++) {
        const int gm = m0 + mbase + mt * 16 + lrow;
#pragma unroll
        for (int nt = 0; nt < 4; nt++) {
            const int gn = n0 + nbase + nt * 8 + lcol;
            if (MODE == 0) {
                const float b0 = bias[gn], b1 = bias[gn + 1];
                float2 v0 = {acc[mt][nt][0] + b0, acc[mt][nt][1] + b1};
                float2 v1 = {acc[mt][nt][2] + b0, acc[mt][nt][3] + b1};
                *(float2*)&C[(size_t)gm * D_MODEL + gn] = v0;
                *(float2*)&C[(size_t)(gm + 8) * D_MODEL + gn] = v1;
            } else {
                const float b0 = bias[gn], b1 = bias[gn + 1];
                const int sec = gn >> 10, fr = gn & 1023;
                const int hh = fr >> 6, dd = fr & 63;
#pragma unroll
                for (int e2 = 0; e2 < 2; e2++) {
                    const int row = gm + e2 * 8;
                    const int bb = row >> 11, s = row & 2047;
                    float2 w = {acc[mt][nt][e2 * 2 + 0] + b0,
                                acc[mt][nt][e2 * 2 + 1] + b1};
                    const size_t base = (((size_t)bb * NH + hh) * S_LEN + s) * HD + dd;
                    if (sec == 0) {
                        *(uint32_t*)&g_qh[base] = h2pack(w.x * 0.125f, w.y * 0.125f);
                    } else {
                        const size_t kvb =
                            ((((size_t)bb * 2 + (sec - 1)) * NH + hh) * S_LEN + s) * HD + dd;
                        *(float2*)&KV[kvb] = w;    // fp32 `present`
                        if (sec == 1) *(uint32_t*)&g_kh[base] = h2pack(w.x, w.y);
                        else          *(uint32_t*)&g_vh[base] = h2pack(w.x, w.y);
                    }
                }
            }
        }
    }
}

// ---------------- tensor-core flash attention, K/V tile double-buffered (R16) ----------------
// Smem: Q (9216) + 2 x (K+V) stages (2 x 18432) = 46080 B -> 4 CTAs/SM.
#define ATTN_SMEM_BYTES 46080

__global__ __launch_bounds__(128, 4) void attn_k()
{
    extern __shared__ char smem[];
    const uint32_t sb = smem_u32(smem);
    const uint32_t sQ = sb;

    const int bid = blockIdx.x;
    const int qt = bid & 31;
    const int h  = (bid >> 5) & 15;
    const int b  = bid >> 9;
    const int qs = qt * 64;

    const int tid = threadIdx.x;
    const int wid = tid >> 5, lid = tid & 31;
    const int mbase = wid * 16;

    const __half* Qg = g_qh + ((size_t)(b * NH + h) * S_LEN + qs) * HD;
    const __half* Kg = g_kh + ((size_t)(b * NH + h) * S_LEN) * HD;
    const __half* Vg = g_vh + ((size_t)(b * NH + h) * S_LEN) * HD;

    const int start = (qs < 256) ? ((256 - qs) >> 6) : 0;

    for (int idx = tid; idx < 512; idx += 128) {
        const int row = idx >> 3, seg = idx & 7;
        cp16(sQ + row * 144 + seg * 16, (const char*)Qg + row * 128 + seg * 16);
    }

#define LOAD_TILE(kt, buf)                                                          \
    {                                                                               \
        const int ks_ = qs - 256 + (kt) * 64;                                       \
        const uint32_t kbuf = sb + 9216 + (buf) * 18432;                            \
        for (int idx = tid; idx < 512; idx += 128) {                                \
            const int row = idx >> 3, seg = idx & 7;                                \
            const int gj = ks_ + row;                                               \
            if (gj >= 0) {                                                          \
                cp16(kbuf + row * 144 + seg * 16,                                   \
                     (const char*)Kg + (size_t)gj * 128 + seg * 16);                \
                cp16(kbuf + 9216 + row * 144 + seg * 16,                            \
                     (const char*)Vg + (size_t)gj * 128 + seg * 16);                \
            } else {                                                                \
                uint4 z = {0u, 0u, 0u, 0u};                                         \
                *(uint4*)(smem + 9216 + (buf) * 18432 + row * 144 + seg * 16) = z;  \
                *(uint4*)(smem + 9216 + (buf) * 18432 + 9216 + row * 144 + seg * 16) = z; \
            }                                                                       \
        }                                                                           \
    }

    LOAD_TILE(start, start & 1);
    CP_COMMIT();

    const uint32_t a_off = (uint32_t)((mbase + ((lid >> 3) & 1) * 8 + (lid & 7)) * 144
                                      + ((lid >> 4) * 8) * 2);
    const uint32_t bK_off = (uint32_t)(((((lid >> 4) & 1) * 8) + (lid & 7)) * 144
                                       + (((lid >> 3) & 1) * 8) * 2);
    const int vmid = lid >> 3;
    const uint32_t bV_off = (uint32_t)((((vmid & 1) * 8 + (lid & 7)) * 144)
                                       + ((vmid >> 1) * 8) * 2);

    const int r0 = lid >> 2;
    const int qcol = (lid & 3) * 2;

    float o[8][4];
#pragma unroll
    for (int t = 0; t < 8; t++)
#pragma unroll
        for (int i = 0; i < 4; i++) o[t][i] = 0.f;
    float m0r = -1e29f, m1r = -1e29f, rs0 = 0.f, rs1 = 0.f;

    for (int kt = start; kt < 5; kt++) {
        const int ks = qs - 256 + kt * 64;

        if (kt + 1 < 5) {
            LOAD_TILE(kt + 1, (kt + 1) & 1);
            CP_COMMIT();
            CP_WAIT1();
        } else {
            CP_WAIT0();
        }
        __syncthreads();

        const uint32_t sK = sb + 9216 + (kt & 1) * 18432;
        const uint32_t sV = sK + 9216;

        float c[8][4];
#pragma unroll
        for (int t = 0; t < 8; t++)
#pragma unroll
            for (int i = 0; i < 4; i++) c[t][i] = 0.f;
#pragma unroll
        for (int ks4 = 0; ks4 < 4; ks4++) {
            const uint32_t kb = (uint32_t)ks4 * 32;
            uint32_t aq[4];
            ldmx4(aq, sQ + a_off + kb);
            uint32_t bk[8][2];
#pragma unroll
            for (int p = 0; p < 4; p++) {
                uint32_t r[4];
                ldmx4(r, sK + bK_off + p * (16 * 144) + kb);
                bk[p * 2][0] = r[0]; bk[p * 2][1] = r[1];
                bk[p * 2 + 1][0] = r[2]; bk[p * 2 + 1][1] = r[3];
            }
#pragma unroll
            for (int t = 0; t < 8; t++)
                mma16816(c[t], aq, bk[t]);
        }

        const int gi0 = qs + mbase + r0, gi1 = gi0 + 8;
#pragma unroll
        for (int t = 0; t < 8; t++) {
            const int cb = ks + t * 8 + qcol;
#pragma unroll
            for (int e = 0; e < 2; e++) {
                const int gj = cb + e;
                if (!(gj >= 0 && gj <= gi0 && gj > gi0 - WINDOW)) c[t][e]     = -1e30f;
                if (!(gj >= 0 && gj <= gi1 && gj > gi1 - WINDOW)) c[t][e + 2] = -1e30f;
            }
        }

        float mx0 = -1e30f, mx1 = -1e30f;
#pragma unroll
        for (int t = 0; t < 8; t++) {
            mx0 = fmaxf(mx0, fmaxf(c[t][0], c[t][1]));
            mx1 = fmaxf(mx1, fmaxf(c[t][2], c[t][3]));
        }
#pragma unroll
        for (int w = 1; w < 4; w <<= 1) {
            mx0 = fmaxf(mx0, __shfl_xor_sync(0xffffffffu, mx0, w));
            mx1 = fmaxf(mx1, __shfl_xor_sync(0xffffffffu, mx1, w));
        }
        const float mn0 = fmaxf(m0r, mx0), mn1 = fmaxf(m1r, mx1);
        const float al0 = __expf(m0r - mn0), al1 = __expf(m1r - mn1);

        uint32_t pa[4][4];
        float ls0 = 0.f, ls1 = 0.f;
#pragma unroll
        for (int t = 0; t < 8; t++) {
            const float p0 = __expf(c[t][0] - mn0);
            const float p1 = __expf(c[t][1] - mn0);
            const float p2 = __expf(c[t][2] - mn1);
            const float p3 = __expf(c[t][3] - mn1);
            ls0 += p0 + p1; ls1 += p2 + p3;
            pa[t >> 1][(t & 1) * 2 + 0] = h2pack(p0, p1);
            pa[t >> 1][(t & 1) * 2 + 1] = h2pack(p2, p3);
        }
#pragma unroll
        for (int w = 1; w < 4; w <<= 1) {
            ls0 += __shfl_xor_sync(0xffffffffu, ls0, w);
            ls1 += __shfl_xor_sync(0xffffffffu, ls1, w);
        }
        rs0 = rs0 * al0 + ls0;
        rs1 = rs1 * al1 + ls1;
        m0r = mn0; m1r = mn1;
#pragma unroll
        for (int t = 0; t < 8; t++) {
            o[t][0] *= al0; o[t][1] *= al0;
            o[t][2] *= al1; o[t][3] *= al1;
        }

#pragma unroll
        for (int kk = 0; kk < 4; kk++) {
            uint32_t bv[8][2];
#pragma unroll
            for (int p = 0; p < 4; p++) {
                uint32_t r[4];
                ldmx4t(r, sV + bV_off + kk * (16 * 144) + p * 32);
                bv[p * 2][0] = r[0]; bv[p * 2][1] = r[1];
                bv[p * 2 + 1][0] = r[2]; bv[p * 2 + 1][1] = r[3];
            }
#pragma unroll
            for (int t = 0; t < 8; t++)
                mma16816(o[t], pa[kk], bv[t]);
        }
        __syncthreads();
    }
#undef LOAD_TILE

    const float ri0 = 1.f / rs0, ri1 = 1.f / rs1;
    const size_t mrow0 = (size_t)b * S_LEN + qs + mbase + r0;
    __half* row0 = g_ah + mrow0 * D_MODEL;
    __half* row1 = row0 + (size_t)8 * D_MODEL;
    const int kc = h * HD + qcol;
#pragma unroll
    for (int t = 0; t < 8; t++) {
        const int k = kc + t * 8;
        *(uint32_t*)&row0[k] = h2pack(o[t][0] * ri0, o[t][1] * ri0);
        *(uint32_t*)&row1[k] = h2pack(o[t][2] * ri1, o[t][3] * ri1);
    }
}

// ---------------------------------------------------------------------------
extern "C" void kernel_launch(void* const* d_in, const int* in_sizes, int n_in,
                              void* d_out, int out_size)
{
    const float* x      = (const float*)d_in[0];
    const float* w_attn = (const float*)d_in[1];
    const float* b_attn = (const float*)d_in[2];
    const float* w_proj = (const float*)d_in[3];
    const float* b_proj = (const float*)d_in[4];
    float* out = (float*)d_out;
    float* kv  = out + OUT_ELEMS;

    cudaFuncSetAttribute(attn_k, cudaFuncAttributeMaxDynamicSharedMemorySize, ATTN_SMEM_BYTES);
    cudaFuncSetAttribute(gemm_mma<0>, cudaFuncAttributeMaxDynamicSharedMemorySize, GEMM_SMEM);
    cudaFuncSetAttribute(gemm_mma<1>, cudaFuncAttributeMaxDynamicSharedMemorySize, GEMM_SMEM);

    __half *xh, *ah, *wat, *wpt;
    cudaGetSymbolAddress((void**)&xh,  g_xh);
    cudaGetSymbolAddress((void**)&ah,  g_ah);
    cudaGetSymbolAddress((void**)&wat, g_wat);
    cudaGetSymbolAddress((void**)&wpt, g_wpt);

    // 1) conversions: x, w_attn^T, w_proj^T -> fp16 hi
    convAh_k<<<(TOKENS * 256 + 255) / 256, 256>>>(x, xh, TOKENS * 256);
    {
        dim3 blk(8, 32);
        convBth_k<<<dim3(3 * D_MODEL / 32, D_MODEL / 32), blk>>>(w_attn, wat, 3 * D_MODEL);
        convBth_k<<<dim3(D_MODEL / 32, D_MODEL / 32),     blk>>>(w_proj, wpt, D_MODEL);
    }

    // 2) QKV projection (K=1024, 128x128 tiles): fp16 Q/K/V + fp32 present tail
    gemm_mma<1><<<dim3(3 * D_MODEL / 128, TOKENS / 128), 256, GEMM_SMEM>>>(
        xh, wat, b_attn, nullptr, kv);

    // 3) tensor-core flash attention (double-buffered K/V) -> g_ah
    attn_k<<<BATCH * NH * (S_LEN / 64), 128, ATTN_SMEM_BYTES>>>();

    // 4) output projection (K=1024) -> d_out head
    gemm_mma<0><<<dim3(D_MODEL / 128, TOKENS / 128), 256, GEMM_SMEM>>>(
        ah, wpt, b_proj, out, nullptr);
}